// round 15
// baseline (speedup 1.0000x reference)
#include <cuda_runtime.h>
#include <cuda_bf16.h>
#include <cstdint>

#define B_   32
#define D_   256
#define HW_  1024
#define N_   32768
#define K_   1024
#define MARGIN 3e-4f
#define FINF 3.4e38f

static const long long Q_OFF = 8388608LL;   // B*D*H*W

// ---------------- device globals ----------------
__device__ int    g_idx[N_];
__device__ float  g_c2[K_];
__device__ float  g_x2[N_];
__device__ double g_acc;
__device__ __align__(16) float         g_xt[(size_t)N_ * D_];
__device__ __align__(16) __nv_bfloat16 g_xh[(size_t)N_ * D_];
__device__ __align__(16) __nv_bfloat16 g_ch[(size_t)K_ * D_];
__device__ float g_cv[N_][4];   // written only for queue-A rows (c2 - 2s)
__device__ int   g_ci[N_][4];
__device__ int   g_qa[N_];
__device__ int   g_qb[N_];
__device__ int   g_qa_n;
__device__ int   g_qb_n;

__device__ __forceinline__ uint32_t smem_u32(const void* p) {
    uint32_t a;
    asm("{ .reg .u64 t; cvta.to.shared.u64 t, %1; cvt.u32.u64 %0, t; }"
        : "=r"(a) : "l"(p));
    return a;
}
#define LDSM_X4(r0, r1, r2, r3, addr) \
    asm volatile("ldmatrix.sync.aligned.m8n8.x4.shared.b16 {%0,%1,%2,%3}, [%4];" \
                 : "=r"(r0), "=r"(r1), "=r"(r2), "=r"(r3) : "r"(addr))
#define MMA_BF16(c, a0, a1, a2, a3, b0, b1) \
    asm volatile("mma.sync.aligned.m16n8k16.row.col.f32.bf16.bf16.f32 " \
                 "{%0,%1,%2,%3}, {%4,%5,%6,%7}, {%8,%9}, {%0,%1,%2,%3};" \
                 : "+f"((c)[0]), "+f"((c)[1]), "+f"((c)[2]), "+f"((c)[3]) \
                 : "r"(a0), "r"(a1), "r"(a2), "r"(a3), "r"(b0), "r"(b1))
#define CP_ASYNC16(dst, src) \
    asm volatile("cp.async.cg.shared.global [%0], [%1], 16;" \
                 :: "r"(dst), "l"(src))
#define CP_COMMIT() asm volatile("cp.async.commit_group;" ::: "memory")
#define CP_WAIT(n)  asm volatile("cp.async.wait_group %0;" :: "n"(n) : "memory")

__device__ __forceinline__ void fold4(float* v, int* ix, float nv, int nk) {
    if (nv < v[3]) {
        if (nv < v[2]) {
            v[3] = v[2]; ix[3] = ix[2];
            if (nv < v[1]) {
                v[2] = v[1]; ix[2] = ix[1];
                if (nv < v[0]) { v[1] = v[0]; ix[1] = ix[0]; v[0] = nv; ix[0] = nk; }
                else           { v[1] = nv; ix[1] = nk; }
            } else { v[2] = nv; ix[2] = nk; }
        } else { v[3] = nv; ix[3] = nk; }
    }
}

// ---------------------------------------------------------------------------
// prep_cb: bf16 hi split; exact c2 (sequential no-FMA); resets accumulators.
// ---------------------------------------------------------------------------
__global__ __launch_bounds__(256) void prep_cb(const float* __restrict__ cb) {
    __shared__ float row[256];
    const int k = blockIdx.x, t = threadIdx.x;
    if (k == 0 && t == 0) { g_acc = 0.0; g_qa_n = 0; g_qb_n = 0; }
    const float v = cb[(size_t)k * D_ + t];
    row[t] = v;
    g_ch[(size_t)k * D_ + t] = __float2bfloat16(v);
    __syncthreads();
    if (t == 0) {
        float s = 0.f;
        for (int d = 0; d < D_; ++d)
            s = __fadd_rn(s, __fmul_rn(row[d], row[d]));
        g_c2[k] = s;
    }
}

// ---------------------------------------------------------------------------
// prep_x: float4 transpose loads, x2 chain on warps 0-1 (others bypass),
// packed float2/bf16x2 writes. dyn smem: 64*257 floats.
// ---------------------------------------------------------------------------
__global__ __launch_bounds__(256) void prep_x(const float* __restrict__ x) {
    extern __shared__ float xs[];   // [64 n][257 d]
    const int t   = threadIdx.x;
    const int n0  = blockIdx.x * 64;
    const int b   = n0 >> 10;
    const int hw0 = n0 & 1023;
    const float* xb = x + ((size_t)b << 18) + hw0;

#pragma unroll
    for (int i = 0; i < 16; ++i) {
        const int e  = t + (i << 8);
        const int d  = e >> 4;
        const int n4 = (e & 15) << 2;
        const float4 v = *(const float4*)(xb + ((size_t)d << 10) + n4);
        xs[(n4 + 0) * 257 + d] = v.x;
        xs[(n4 + 1) * 257 + d] = v.y;
        xs[(n4 + 2) * 257 + d] = v.z;
        xs[(n4 + 3) * 257 + d] = v.w;
    }
    __syncthreads();

    if (t < 64) {
        const float* r = xs + t * 257;
        float s = 0.f;
        for (int d = 0; d < D_; ++d)
            s = __fadd_rn(s, __fmul_rn(r[d], r[d]));
        g_x2[n0 + t] = s;
    }

#pragma unroll
    for (int i = 0; i < 32; ++i) {
        const int e  = t + (i << 8);
        const int n  = e >> 7;
        const int d2 = (e & 127) << 1;
        const float v0 = xs[n * 257 + d2];
        const float v1 = xs[n * 257 + d2 + 1];
        const size_t gi = ((size_t)(n0 + n) << 8) + d2;
        *(float2*)(g_xt + gi) = make_float2(v0, v1);
        __nv_bfloat162 hp;
        hp.x = __float2bfloat16(v0);
        hp.y = __float2bfloat16(v1);
        *(__nv_bfloat162*)(g_xh + gi) = hp;
    }
}

// ---------------------------------------------------------------------------
// gemm_argmin: single-pass HMMA (s = xh*ch), x2-free epilogue with
// branch-elision guard (fminf over the 8 row values; fold only if the
// group min beats the current 4th-best — provably outcome-identical).
// Classification fused into the tail: g_idx direct for unambiguous rows,
// queue A/B compaction for the rest. 128-row CTA, 512 threads.
// ---------------------------------------------------------------------------
#define PITCH 264
#define SA        0
#define SB        (128 * PITCH * 2)               // 67584
#define SB_STRIDE (128 * PITCH * 2)               // 67584 per buffer
#define S_C2      (SB + 2 * SB_STRIDE)            // 202752
#define S_MGV     (S_C2 + 4096)                   // 206848 (128*4*4 floats)
#define S_MGI     (S_MGV + 8192)                  // 215040
#define GEMM_SMEM (S_MGI + 8192)                  // 223232

__device__ __forceinline__ void stage_b(uint32_t sb, int buf, int kc, int t) {
    const uint32_t dst = sb + SB + buf * SB_STRIDE;
#pragma unroll
    for (int i = 0; i < 8; ++i) {
        const int e = t + (i << 9);               // 0..4095
        const int row = e >> 5;                   // 0..127
        const int c8 = (e & 31) << 3;             // 0..248
        CP_ASYNC16(dst + (uint32_t)(row * PITCH + c8) * 2,
                   g_ch + (((size_t)((kc << 7) + row)) << 8) + c8);
    }
}

__global__ __launch_bounds__(512, 1) void gemm_argmin() {
    extern __shared__ char sm[];
    __nv_bfloat16* Ah = (__nv_bfloat16*)(sm + SA);
    float* c2s = (float*)(sm + S_C2);
    float* mgv = (float*)(sm + S_MGV);
    int*   mgi = (int*)(sm + S_MGI);

    const int t    = threadIdx.x;
    const int lane = t & 31;
    const int w    = t >> 5;                      // 0..15
    const int wm   = (w >> 2) << 5;               // M base row: 0,32,64,96
    const int wq   = w & 3;                       // N quarter of 128-chunk
    const int n0   = blockIdx.x * 128;
    const int g = lane >> 2, q = lane & 3;
    const uint32_t sb = smem_u32(sm);

    stage_b(sb, 0, 0, t);
    CP_COMMIT();

    // resident A (hi), c2
#pragma unroll
    for (int i = 0; i < 8; ++i) {
        const int e = t + (i << 9);
        const int row = e >> 5, c8 = (e & 31) << 3;
        *(uint4*)(Ah + row * PITCH + c8) =
            *(const uint4*)(g_xh + ((size_t)(n0 + row) << 8) + c8);
    }
#pragma unroll
    for (int i = 0; i < 2; ++i) c2s[t + (i << 9)] = g_c2[t + (i << 9)];

    const uint32_t a_idx = (uint32_t)((wm + (lane & 15)) * PITCH + ((lane >> 4) << 3));
    const uint32_t aoh = sb + SA + a_idx * 2;
    const uint32_t b_idx = (uint32_t)(((lane & 7) + ((lane >> 4) << 3)) * PITCH
                                      + (((lane >> 3) & 1) << 3));
    const uint32_t bgrp = (uint32_t)((wq << 5) * PITCH) * 2;   // N-quarter offset
    const int col_off = (wq << 5) + (q << 1);

    float tv[4][4];
    int   ti[4][4];
#pragma unroll
    for (int r = 0; r < 4; ++r)
#pragma unroll
        for (int s = 0; s < 4; ++s) { tv[r][s] = FINF; ti[r][s] = 0; }

    for (int nc = 0; nc < 8; ++nc) {
        const int buf = nc & 1;
        if (nc < 7) { stage_b(sb, buf ^ 1, nc + 1, t); CP_COMMIT(); CP_WAIT(1); }
        else        { CP_WAIT(0); }
        __syncthreads();

        const uint32_t bh = sb + SB + buf * SB_STRIDE + bgrp + b_idx * 2;

        float acc[2][4][4];
#pragma unroll
        for (int mh = 0; mh < 2; ++mh)
#pragma unroll
            for (int j = 0; j < 4; ++j)
#pragma unroll
                for (int s = 0; s < 4; ++s) acc[mh][j][s] = 0.f;

#pragma unroll 8
        for (int k = 0; k < 16; ++k) {
            uint32_t a00, a01, a02, a03, a10, a11, a12, a13;
            uint32_t h00, h01, h02, h03, h10, h11, h12, h13;
            LDSM_X4(a00, a01, a02, a03, aoh + k * 32);
            LDSM_X4(a10, a11, a12, a13, aoh + 16 * PITCH * 2 + k * 32);
            LDSM_X4(h00, h01, h02, h03, bh + k * 32);
            LDSM_X4(h10, h11, h12, h13, bh + 16 * PITCH * 2 + k * 32);
            MMA_BF16(acc[0][0], a00, a01, a02, a03, h00, h01);
            MMA_BF16(acc[0][1], a00, a01, a02, a03, h02, h03);
            MMA_BF16(acc[0][2], a00, a01, a02, a03, h10, h11);
            MMA_BF16(acc[0][3], a00, a01, a02, a03, h12, h13);
            MMA_BF16(acc[1][0], a10, a11, a12, a13, h00, h01);
            MMA_BF16(acc[1][1], a10, a11, a12, a13, h02, h03);
            MMA_BF16(acc[1][2], a10, a11, a12, a13, h10, h11);
            MMA_BF16(acc[1][3], a10, a11, a12, a13, h12, h13);
        }

        // epilogue: v = fmaf(-2, s, c2); per-row fminf guard elides folds
        const int colb0 = (nc << 7) + col_off;
#pragma unroll
        for (int mh = 0; mh < 2; ++mh) {
#pragma unroll
            for (int half = 0; half < 2; ++half) {   // row tv[mh*2+half]
                const int r = mh * 2 + half;
                float vv[8];
#pragma unroll
                for (int j = 0; j < 4; ++j) {
                    const int colb = colb0 + (j << 3);
                    vv[2 * j]     = fmaf(-2.f, acc[mh][j][2 * half],     c2s[colb]);
                    vv[2 * j + 1] = fmaf(-2.f, acc[mh][j][2 * half + 1], c2s[colb + 1]);
                }
                float vmin = vv[0];
#pragma unroll
                for (int s = 1; s < 8; ++s) vmin = fminf(vmin, vv[s]);
                if (vmin < tv[r][3]) {
#pragma unroll
                    for (int j = 0; j < 4; ++j) {
                        const int colb = colb0 + (j << 3);
                        fold4(tv[r], ti[r], vv[2 * j],     colb);
                        fold4(tv[r], ti[r], vv[2 * j + 1], colb + 1);
                    }
                }
            }
        }
        __syncthreads();        // buf fully consumed before it is re-staged
    }

    // merge across the 4 q-lanes via shuffles
#pragma unroll
    for (int r = 0; r < 4; ++r) {
#pragma unroll
        for (int m = 1; m <= 2; m <<= 1) {
            float ov[4]; int oi[4];
#pragma unroll
            for (int s = 0; s < 4; ++s) {
                ov[s] = __shfl_xor_sync(0xffffffffu, tv[r][s], m);
                oi[s] = __shfl_xor_sync(0xffffffffu, ti[r][s], m);
            }
#pragma unroll
            for (int s = 0; s < 4; ++s) fold4(tv[r], ti[r], ov[s], oi[s]);
        }
    }
    if (q == 0) {
#pragma unroll
        for (int r = 0; r < 4; ++r) {
            const int row = wm + ((r & 1) << 3) + ((r >> 1) << 4) + g;
#pragma unroll
            for (int s = 0; s < 4; ++s) {
                mgv[(row * 4 + wq) * 4 + s] = tv[r][s];
                mgi[(row * 4 + wq) * 4 + s] = ti[r][s];
            }
        }
    }
    __syncthreads();
    if (t < 128) {
        float bv[4] = {FINF, FINF, FINF, FINF};
        int   bi[4] = {0, 0, 0, 0};
#pragma unroll
        for (int qq = 0; qq < 4; ++qq)
#pragma unroll
            for (int s = 0; s < 4; ++s)
                fold4(bv, bi, mgv[(t * 4 + qq) * 4 + s], mgi[(t * 4 + qq) * 4 + s]);
        const int n = n0 + t;
        // fused classification
        const float lim = bv[0] + MARGIN;
        const int ncand = 1 + (bv[1] <= lim) + (bv[2] <= lim) + (bv[3] <= lim);
        if (ncand == 1) {
            g_idx[n] = bi[0];
        } else if (ncand < 4) {
#pragma unroll
            for (int s = 0; s < 4; ++s) { g_cv[n][s] = bv[s]; g_ci[n][s] = bi[s]; }
            g_qa[atomicAdd(&g_qa_n, 1)] = n;
        } else {
            g_qb[atomicAdd(&g_qb_n, 1)] = n;
        }
    }
}

// ---------------------------------------------------------------------------
// refine_small: persistent warps grid-stride over queue A (2-3 candidates).
// ---------------------------------------------------------------------------
__global__ __launch_bounds__(256) void refine_small(const float* __restrict__ cb)
{
    __shared__ float sx[8][260];
    __shared__ float sc[8][3][260];
    const int w = threadIdx.x >> 5;
    const int l = threadIdx.x & 31;
    const int wi = (blockIdx.x << 3) + w;
    const int stride = gridDim.x << 3;
    const int cnt = g_qa_n;

    for (int i = wi; i < cnt; i += stride) {
        const int n = g_qa[i];
        const float lim = g_cv[n][0] + MARGIN;
        const int ncand = 2 + (g_cv[n][2] <= lim);

        {
            const float* xr = g_xt + ((size_t)n << 8);
#pragma unroll
            for (int ii = 0; ii < 2; ++ii) {
                const int d = (l + (ii << 5)) << 2;
                *(float4*)&sx[w][d] = *(const float4*)(xr + d);
            }
        }
        for (int c = 0; c < ncand; ++c) {
            const float* cr = cb + ((size_t)g_ci[n][c] << 8);
#pragma unroll
            for (int ii = 0; ii < 2; ++ii) {
                const int d = (l + (ii << 5)) << 2;
                *(float4*)&sc[w][c][d] = *(const float4*)(cr + d);
            }
        }
        __syncwarp();

        float bestv = FINF;
        int   besti = 0x7fffffff;
        if (l < ncand) {
            const int k = g_ci[n][l];
            float s = 0.f;
#pragma unroll 16
            for (int d = 0; d < D_; ++d)
                s = fmaf(sx[w][d], sc[w][l][d], s);
            bestv = __fadd_rn(__fadd_rn(g_x2[n], -2.f * s), g_c2[k]);
            besti = k;
        }
#pragma unroll
        for (int m = 16; m; m >>= 1) {
            const float ov = __shfl_xor_sync(0xffffffffu, bestv, m);
            const int   oi = __shfl_xor_sync(0xffffffffu, besti, m);
            if (ov < bestv || (ov == bestv && oi < besti)) { bestv = ov; besti = oi; }
        }
        if (l == 0) g_idx[n] = besti;
        __syncwarp();
    }
}

// ---------------------------------------------------------------------------
// refine_full (batched): 8 saturated rows per block share each staged
// 64-code chunk. Exact chains, first-min tie-break. dyn smem: 64*257 floats.
// ---------------------------------------------------------------------------
__global__ __launch_bounds__(256) void refine_full(const float* __restrict__ cb)
{
    extern __shared__ float scf[];          // [64][257]
    __shared__ float sx[8][260];
    __shared__ float x2s[8];
    __shared__ int   rown[8];
    __shared__ float c2s[K_];
    __shared__ float bvS[8][64];
    __shared__ int   biS[8][64];
    const int t = threadIdx.x;
    const int cnt = g_qb_n;
    const int c = t & 63, r = t >> 6;

#pragma unroll
    for (int i = 0; i < 4; ++i) c2s[t + (i << 8)] = g_c2[t + (i << 8)];

    for (int q0 = blockIdx.x * 8; q0 < cnt; q0 += gridDim.x * 8) {
        const int nrows = min(8, cnt - q0);
        __syncthreads();
        if (t < 8 && t < nrows) {
            const int n = g_qb[q0 + t];
            rown[t] = n;
            x2s[t] = g_x2[n];
        }
#pragma unroll
        for (int i = 0; i < 2; ++i) {
            const int slot = t + (i << 8);
            const int rr = slot >> 6, d4 = (slot & 63) << 2;
            if (rr < nrows) {
                const int n = g_qb[q0 + rr];
                *(float4*)&sx[rr][d4] = *(const float4*)(g_xt + ((size_t)n << 8) + d4);
            }
        }

        float bv0 = FINF, bv1 = FINF;
        int   bi0 = 0x7fffffff, bi1 = 0x7fffffff;

        for (int nc = 0; nc < 16; ++nc) {
            __syncthreads();
#pragma unroll
            for (int i = 0; i < 16; ++i) {
                const int e = t + (i << 8);
                const int row = e >> 6, c4 = (e & 63) << 2;
                const float4 v = *(const float4*)(cb + ((size_t)((nc << 6) + row) << 8) + c4);
                float* dst = scf + row * 257 + c4;
                dst[0] = v.x; dst[1] = v.y; dst[2] = v.z; dst[3] = v.w;
            }
            __syncthreads();
            const int k = (nc << 6) + c;
            const float* cr = scf + c * 257;
            float s0 = 0.f, s1 = 0.f;
#pragma unroll 8
            for (int d = 0; d < D_; ++d) {
                const float cv = cr[d];
                s0 = fmaf(sx[r][d],     cv, s0);
                s1 = fmaf(sx[r + 4][d], cv, s1);
            }
            const float v0 = __fadd_rn(__fadd_rn(x2s[r],     -2.f * s0), c2s[k]);
            const float v1 = __fadd_rn(__fadd_rn(x2s[r + 4], -2.f * s1), c2s[k]);
            if (v0 < bv0) { bv0 = v0; bi0 = k; }
            if (v1 < bv1) { bv1 = v1; bi1 = k; }
        }

        bvS[r][c] = bv0;     biS[r][c] = bi0;
        bvS[r + 4][c] = bv1; biS[r + 4][c] = bi1;
        __syncthreads();

        const int w = t >> 5, l = t & 31;
        if (w < nrows) {
            float v = bvS[w][l];        int kk = biS[w][l];
            const float v2 = bvS[w][l + 32]; const int k2 = biS[w][l + 32];
            if (v2 < v || (v2 == v && k2 < kk)) { v = v2; kk = k2; }
#pragma unroll
            for (int m = 16; m; m >>= 1) {
                const float ov = __shfl_xor_sync(0xffffffffu, v, m);
                const int   oi = __shfl_xor_sync(0xffffffffu, kk, m);
                if (ov < v || (ov == v && oi < kk)) { v = ov; kk = oi; }
            }
            if (l == 0) g_idx[rown[w]] = kk;
        }
    }
}

// ---------------------------------------------------------------------------
// quant: gathered codebook rows staged to smem, straight-through output +
// loss partials + idx-as-float. dyn smem: 64*257 floats.
// ---------------------------------------------------------------------------
__global__ __launch_bounds__(256) void quant_kernel(
    const float* __restrict__ x, const float* __restrict__ cb,
    float* __restrict__ out, long long out_size)
{
    extern __shared__ float sc[];           // [64][257]
    __shared__ float red[256];
    __shared__ int   ks[64];
    const int t   = threadIdx.x;
    const int n0  = blockIdx.x * 64;
    const int b   = n0 / HW_;
    const int hw0 = n0 % HW_;
    const int tn  = t & 63;
    const int dz  = t >> 6;
    const int n   = n0 + tn;

    if (t < 64) ks[t] = g_idx[n0 + t];
    __syncthreads();

#pragma unroll
    for (int i = 0; i < 16; ++i) {
        const int e = t + (i << 8);
        const int row = e >> 6, f4 = (e & 63) << 2;
        const float4 v = *(const float4*)(cb + ((size_t)ks[row] << 8) + f4);
        float* dst = sc + row * 257 + f4;
        dst[0] = v.x; dst[1] = v.y; dst[2] = v.z; dst[3] = v.w;
    }
    __syncthreads();

    const float* xb = x   + (size_t)b * D_ * HW_ + hw0 + tn;
    float*       ob = out + (size_t)b * D_ * HW_ + hw0 + tn;
    const float* cr = sc + tn * 257;

    float s = 0.f;
#pragma unroll 8
    for (int d = dz; d < D_; d += 4) {
        const float xv   = xb[(size_t)d * HW_];
        const float cv   = cr[d];
        const float diff = __fadd_rn(cv, -xv);
        ob[(size_t)d * HW_] = __fadd_rn(xv, diff);
        s = fmaf(diff, diff, s);
    }

    if (dz == 0 && out_size >= Q_OFF + 3 + N_)
        out[Q_OFF + 3 + n] = (float)ks[tn];

    red[t] = s;
    __syncthreads();
    for (int w = 128; w > 0; w >>= 1) {
        if (t < w) red[t] += red[t + w];
        __syncthreads();
    }
    if (t == 0) atomicAdd(&g_acc, (double)red[0]);
}

__global__ void finalize_kernel(float* __restrict__ out, long long out_size) {
    if (out_size >= Q_OFF + 3) {
        const double m = g_acc / (double)((long long)N_ * D_);
        const float  l = (float)m;
        out[Q_OFF + 0] = l;
        out[Q_OFF + 1] = l;
        out[Q_OFF + 2] = __fadd_rn(l, 0.25f * l);
    }
}

// ---------------------------------------------------------------------------
extern "C" void kernel_launch(void* const* d_in, const int* in_sizes, int n_in,
                              void* d_out, int out_size)
{
    const float* x  = (const float*)d_in[0];
    const float* cb = (const float*)d_in[1];
    float*       out = (float*)d_out;
    const long long osz = (long long)out_size;

    cudaFuncSetAttribute(prep_x,
        cudaFuncAttributeMaxDynamicSharedMemorySize, 64 * 257 * 4);
    cudaFuncSetAttribute(gemm_argmin,
        cudaFuncAttributeMaxDynamicSharedMemorySize, GEMM_SMEM);
    cudaFuncSetAttribute(refine_full,
        cudaFuncAttributeMaxDynamicSharedMemorySize, 64 * 257 * 4);
    cudaFuncSetAttribute(quant_kernel,
        cudaFuncAttributeMaxDynamicSharedMemorySize, 64 * 257 * 4);

    prep_cb<<<K_, 256>>>(cb);                      // launch 1
    prep_x<<<512, 256, 64 * 257 * 4>>>(x);         // launch 2
    gemm_argmin<<<N_ / 128, 512, GEMM_SMEM>>>();   // launch 3
    refine_small<<<256, 256>>>(cb);                // launch 4 (ncu target)
    refine_full<<<64, 256, 64 * 257 * 4>>>(cb);    // launch 5
    quant_kernel<<<N_ / 64, 256, 64 * 257 * 4>>>(x, cb, out, osz);
    finalize_kernel<<<1, 1>>>(out, osz);
}

// round 16
// speedup vs baseline: 1.4106x; 1.4106x over previous
#include <cuda_runtime.h>
#include <cuda_fp16.h>
#include <cstdint>

#define B_   32
#define D_   256
#define HW_  1024
#define N_   32768
#define K_   1024
#define MARGIN 1.2e-4f
#define FINF 3.4e38f

static const long long Q_OFF = 8388608LL;   // B*D*H*W

// ---------------- device globals ----------------
__device__ int    g_idx[N_];
__device__ float  g_c2[K_];
__device__ float  g_x2[N_];
__device__ double g_acc;
__device__ __align__(16) float  g_xt[(size_t)N_ * D_];
__device__ __align__(16) __half g_xh[(size_t)N_ * D_];
__device__ __align__(16) __half g_ch[(size_t)K_ * D_];
__device__ float g_cv[N_][4];   // queue-A rows only (c2 - 2s)
__device__ int   g_ci[N_][4];
__device__ int   g_qa[N_];
__device__ int   g_qb[N_];
__device__ int   g_qa_n;
__device__ int   g_qb_n;

__device__ __forceinline__ uint32_t smem_u32(const void* p) {
    uint32_t a;
    asm("{ .reg .u64 t; cvta.to.shared.u64 t, %1; cvt.u32.u64 %0, t; }"
        : "=r"(a) : "l"(p));
    return a;
}
#define LDSM_X4(r0, r1, r2, r3, addr) \
    asm volatile("ldmatrix.sync.aligned.m8n8.x4.shared.b16 {%0,%1,%2,%3}, [%4];" \
                 : "=r"(r0), "=r"(r1), "=r"(r2), "=r"(r3) : "r"(addr))
#define MMA_F16(c, a0, a1, a2, a3, b0, b1) \
    asm volatile("mma.sync.aligned.m16n8k16.row.col.f32.f16.f16.f32 " \
                 "{%0,%1,%2,%3}, {%4,%5,%6,%7}, {%8,%9}, {%0,%1,%2,%3};" \
                 : "+f"((c)[0]), "+f"((c)[1]), "+f"((c)[2]), "+f"((c)[3]) \
                 : "r"(a0), "r"(a1), "r"(a2), "r"(a3), "r"(b0), "r"(b1))
#define CP_ASYNC16(dst, src) \
    asm volatile("cp.async.cg.shared.global [%0], [%1], 16;" \
                 :: "r"(dst), "l"(src))
#define CP_COMMIT() asm volatile("cp.async.commit_group;" ::: "memory")
#define CP_WAIT(n)  asm volatile("cp.async.wait_group %0;" :: "n"(n) : "memory")

__device__ __forceinline__ void fold4(float* v, int* ix, float nv, int nk) {
    if (nv < v[3]) {
        if (nv < v[2]) {
            v[3] = v[2]; ix[3] = ix[2];
            if (nv < v[1]) {
                v[2] = v[1]; ix[2] = ix[1];
                if (nv < v[0]) { v[1] = v[0]; ix[1] = ix[0]; v[0] = nv; ix[0] = nk; }
                else           { v[1] = nv; ix[1] = nk; }
            } else { v[2] = nv; ix[2] = nk; }
        } else { v[3] = nv; ix[3] = nk; }
    }
}

// ---------------------------------------------------------------------------
// prep_cb: fp16 convert; exact c2 (sequential no-FMA); resets accumulators.
// ---------------------------------------------------------------------------
__global__ __launch_bounds__(256) void prep_cb(const float* __restrict__ cb) {
    __shared__ float row[256];
    const int k = blockIdx.x, t = threadIdx.x;
    if (k == 0 && t == 0) { g_acc = 0.0; g_qa_n = 0; g_qb_n = 0; }
    const float v = cb[(size_t)k * D_ + t];
    row[t] = v;
    g_ch[(size_t)k * D_ + t] = __float2half_rn(v);
    __syncthreads();
    if (t == 0) {
        float s = 0.f;
        for (int d = 0; d < D_; ++d)
            s = __fadd_rn(s, __fmul_rn(row[d], row[d]));
        g_c2[k] = s;
    }
}

// ---------------------------------------------------------------------------
// prep_x: float4 transpose loads, x2 chain on warps 0-1 (others bypass),
// packed float2/half2 writes. dyn smem: 64*257 floats.
// ---------------------------------------------------------------------------
__global__ __launch_bounds__(256) void prep_x(const float* __restrict__ x) {
    extern __shared__ float xs[];   // [64 n][257 d]
    const int t   = threadIdx.x;
    const int n0  = blockIdx.x * 64;
    const int b   = n0 >> 10;
    const int hw0 = n0 & 1023;
    const float* xb = x + ((size_t)b << 18) + hw0;

#pragma unroll
    for (int i = 0; i < 16; ++i) {
        const int e  = t + (i << 8);
        const int d  = e >> 4;
        const int n4 = (e & 15) << 2;
        const float4 v = *(const float4*)(xb + ((size_t)d << 10) + n4);
        xs[(n4 + 0) * 257 + d] = v.x;
        xs[(n4 + 1) * 257 + d] = v.y;
        xs[(n4 + 2) * 257 + d] = v.z;
        xs[(n4 + 3) * 257 + d] = v.w;
    }
    __syncthreads();

    if (t < 64) {
        const float* r = xs + t * 257;
        float s = 0.f;
        for (int d = 0; d < D_; ++d)
            s = __fadd_rn(s, __fmul_rn(r[d], r[d]));
        g_x2[n0 + t] = s;
    }

#pragma unroll
    for (int i = 0; i < 32; ++i) {
        const int e  = t + (i << 8);
        const int n  = e >> 7;
        const int d2 = (e & 127) << 1;
        const float v0 = xs[n * 257 + d2];
        const float v1 = xs[n * 257 + d2 + 1];
        const size_t gi = ((size_t)(n0 + n) << 8) + d2;
        *(float2*)(g_xt + gi) = make_float2(v0, v1);
        *(__half2*)(g_xh + gi) = __floats2half2_rn(v0, v1);
    }
}

// ---------------------------------------------------------------------------
// gemm_argmin: single-pass fp16 HMMA (s = xh*ch), x2-free epilogue with
// fminf branch-elision guard; classification fused into the tail.
// 128-row CTA, 512 threads = 16 warps (4M x 4N), 128-code B chunks
// cp.async double-buffered.
// ---------------------------------------------------------------------------
#define PITCH 264
#define SA        0
#define SB        (128 * PITCH * 2)               // 67584
#define SB_STRIDE (128 * PITCH * 2)               // 67584 per buffer
#define S_C2      (SB + 2 * SB_STRIDE)            // 202752
#define S_MGV     (S_C2 + 4096)                   // 206848
#define S_MGI     (S_MGV + 8192)                  // 215040
#define GEMM_SMEM (S_MGI + 8192)                  // 223232

__device__ __forceinline__ void stage_b(uint32_t sb, int buf, int kc, int t) {
    const uint32_t dst = sb + SB + buf * SB_STRIDE;
#pragma unroll
    for (int i = 0; i < 8; ++i) {
        const int e = t + (i << 9);               // 0..4095
        const int row = e >> 5;                   // 0..127
        const int c8 = (e & 31) << 3;             // 0..248
        CP_ASYNC16(dst + (uint32_t)(row * PITCH + c8) * 2,
                   g_ch + (((size_t)((kc << 7) + row)) << 8) + c8);
    }
}

__global__ __launch_bounds__(512, 1) void gemm_argmin() {
    extern __shared__ char sm[];
    __half* Ah = (__half*)(sm + SA);
    float* c2s = (float*)(sm + S_C2);
    float* mgv = (float*)(sm + S_MGV);
    int*   mgi = (int*)(sm + S_MGI);

    const int t    = threadIdx.x;
    const int lane = t & 31;
    const int w    = t >> 5;                      // 0..15
    const int wm   = (w >> 2) << 5;               // M base row
    const int wq   = w & 3;                       // N quarter
    const int n0   = blockIdx.x * 128;
    const int g = lane >> 2, q = lane & 3;
    const uint32_t sb = smem_u32(sm);

    stage_b(sb, 0, 0, t);
    CP_COMMIT();

#pragma unroll
    for (int i = 0; i < 8; ++i) {
        const int e = t + (i << 9);
        const int row = e >> 5, c8 = (e & 31) << 3;
        *(uint4*)(Ah + row * PITCH + c8) =
            *(const uint4*)(g_xh + ((size_t)(n0 + row) << 8) + c8);
    }
#pragma unroll
    for (int i = 0; i < 2; ++i) c2s[t + (i << 9)] = g_c2[t + (i << 9)];

    const uint32_t a_idx = (uint32_t)((wm + (lane & 15)) * PITCH + ((lane >> 4) << 3));
    const uint32_t aoh = sb + SA + a_idx * 2;
    const uint32_t b_idx = (uint32_t)(((lane & 7) + ((lane >> 4) << 3)) * PITCH
                                      + (((lane >> 3) & 1) << 3));
    const uint32_t bgrp = (uint32_t)((wq << 5) * PITCH) * 2;
    const int col_off = (wq << 5) + (q << 1);

    float tv[4][4];
    int   ti[4][4];
#pragma unroll
    for (int r = 0; r < 4; ++r)
#pragma unroll
        for (int s = 0; s < 4; ++s) { tv[r][s] = FINF; ti[r][s] = 0; }

    for (int nc = 0; nc < 8; ++nc) {
        const int buf = nc & 1;
        if (nc < 7) { stage_b(sb, buf ^ 1, nc + 1, t); CP_COMMIT(); CP_WAIT(1); }
        else        { CP_WAIT(0); }
        __syncthreads();

        const uint32_t bh = sb + SB + buf * SB_STRIDE + bgrp + b_idx * 2;

        float acc[2][4][4];
#pragma unroll
        for (int mh = 0; mh < 2; ++mh)
#pragma unroll
            for (int j = 0; j < 4; ++j)
#pragma unroll
                for (int s = 0; s < 4; ++s) acc[mh][j][s] = 0.f;

#pragma unroll 8
        for (int k = 0; k < 16; ++k) {
            uint32_t a00, a01, a02, a03, a10, a11, a12, a13;
            uint32_t h00, h01, h02, h03, h10, h11, h12, h13;
            LDSM_X4(a00, a01, a02, a03, aoh + k * 32);
            LDSM_X4(a10, a11, a12, a13, aoh + 16 * PITCH * 2 + k * 32);
            LDSM_X4(h00, h01, h02, h03, bh + k * 32);
            LDSM_X4(h10, h11, h12, h13, bh + 16 * PITCH * 2 + k * 32);
            MMA_F16(acc[0][0], a00, a01, a02, a03, h00, h01);
            MMA_F16(acc[0][1], a00, a01, a02, a03, h02, h03);
            MMA_F16(acc[0][2], a00, a01, a02, a03, h10, h11);
            MMA_F16(acc[0][3], a00, a01, a02, a03, h12, h13);
            MMA_F16(acc[1][0], a10, a11, a12, a13, h00, h01);
            MMA_F16(acc[1][1], a10, a11, a12, a13, h02, h03);
            MMA_F16(acc[1][2], a10, a11, a12, a13, h10, h11);
            MMA_F16(acc[1][3], a10, a11, a12, a13, h12, h13);
        }

        // epilogue: v = fmaf(-2, s, c2); fminf guard elides folds
        const int colb0 = (nc << 7) + col_off;
#pragma unroll
        for (int mh = 0; mh < 2; ++mh) {
#pragma unroll
            for (int half = 0; half < 2; ++half) {
                const int r = mh * 2 + half;
                float vv[8];
#pragma unroll
                for (int j = 0; j < 4; ++j) {
                    const int colb = colb0 + (j << 3);
                    vv[2 * j]     = fmaf(-2.f, acc[mh][j][2 * half],     c2s[colb]);
                    vv[2 * j + 1] = fmaf(-2.f, acc[mh][j][2 * half + 1], c2s[colb + 1]);
                }
                float vmin = vv[0];
#pragma unroll
                for (int s = 1; s < 8; ++s) vmin = fminf(vmin, vv[s]);
                if (vmin < tv[r][3]) {
#pragma unroll
                    for (int j = 0; j < 4; ++j) {
                        const int colb = colb0 + (j << 3);
                        fold4(tv[r], ti[r], vv[2 * j],     colb);
                        fold4(tv[r], ti[r], vv[2 * j + 1], colb + 1);
                    }
                }
            }
        }
        __syncthreads();
    }

    // merge across the 4 q-lanes via shuffles
#pragma unroll
    for (int r = 0; r < 4; ++r) {
#pragma unroll
        for (int m = 1; m <= 2; m <<= 1) {
            float ov[4]; int oi[4];
#pragma unroll
            for (int s = 0; s < 4; ++s) {
                ov[s] = __shfl_xor_sync(0xffffffffu, tv[r][s], m);
                oi[s] = __shfl_xor_sync(0xffffffffu, ti[r][s], m);
            }
#pragma unroll
            for (int s = 0; s < 4; ++s) fold4(tv[r], ti[r], ov[s], oi[s]);
        }
    }
    if (q == 0) {
#pragma unroll
        for (int r = 0; r < 4; ++r) {
            const int row = wm + ((r & 1) << 3) + ((r >> 1) << 4) + g;
#pragma unroll
            for (int s = 0; s < 4; ++s) {
                mgv[(row * 4 + wq) * 4 + s] = tv[r][s];
                mgi[(row * 4 + wq) * 4 + s] = ti[r][s];
            }
        }
    }
    __syncthreads();
    if (t < 128) {
        float bv[4] = {FINF, FINF, FINF, FINF};
        int   bi[4] = {0, 0, 0, 0};
#pragma unroll
        for (int qq = 0; qq < 4; ++qq)
#pragma unroll
            for (int s = 0; s < 4; ++s)
                fold4(bv, bi, mgv[(t * 4 + qq) * 4 + s], mgi[(t * 4 + qq) * 4 + s]);
        const int n = n0 + t;
        const float lim = bv[0] + MARGIN;
        const int ncand = 1 + (bv[1] <= lim) + (bv[2] <= lim) + (bv[3] <= lim);
        if (ncand == 1) {
            g_idx[n] = bi[0];
        } else if (ncand < 4) {
#pragma unroll
            for (int s = 0; s < 4; ++s) { g_cv[n][s] = bv[s]; g_ci[n][s] = bi[s]; }
            g_qa[atomicAdd(&g_qa_n, 1)] = n;
        } else {
            g_qb[atomicAdd(&g_qb_n, 1)] = n;
        }
    }
}

// ---------------------------------------------------------------------------
// refine_small: persistent warps grid-stride over queue A (2-3 candidates).
// ---------------------------------------------------------------------------
__global__ __launch_bounds__(256) void refine_small(const float* __restrict__ cb)
{
    __shared__ float sx[8][260];
    __shared__ float sc[8][3][260];
    const int w = threadIdx.x >> 5;
    const int l = threadIdx.x & 31;
    const int wi = (blockIdx.x << 3) + w;
    const int stride = gridDim.x << 3;
    const int cnt = g_qa_n;

    for (int i = wi; i < cnt; i += stride) {
        const int n = g_qa[i];
        const float lim = g_cv[n][0] + MARGIN;
        const int ncand = 2 + (g_cv[n][2] <= lim);

        {
            const float* xr = g_xt + ((size_t)n << 8);
#pragma unroll
            for (int ii = 0; ii < 2; ++ii) {
                const int d = (l + (ii << 5)) << 2;
                *(float4*)&sx[w][d] = *(const float4*)(xr + d);
            }
        }
        for (int c = 0; c < ncand; ++c) {
            const float* cr = cb + ((size_t)g_ci[n][c] << 8);
#pragma unroll
            for (int ii = 0; ii < 2; ++ii) {
                const int d = (l + (ii << 5)) << 2;
                *(float4*)&sc[w][c][d] = *(const float4*)(cr + d);
            }
        }
        __syncwarp();

        float bestv = FINF;
        int   besti = 0x7fffffff;
        if (l < ncand) {
            const int k = g_ci[n][l];
            float s = 0.f;
#pragma unroll 16
            for (int d = 0; d < D_; ++d)
                s = fmaf(sx[w][d], sc[w][l][d], s);
            bestv = __fadd_rn(__fadd_rn(g_x2[n], -2.f * s), g_c2[k]);
            besti = k;
        }
#pragma unroll
        for (int m = 16; m; m >>= 1) {
            const float ov = __shfl_xor_sync(0xffffffffu, bestv, m);
            const int   oi = __shfl_xor_sync(0xffffffffu, besti, m);
            if (ov < bestv || (ov == bestv && oi < besti)) { bestv = ov; besti = oi; }
        }
        if (l == 0) g_idx[n] = besti;
        __syncwarp();
    }
}

// ---------------------------------------------------------------------------
// refine_full (batched): 8 saturated rows per block share each staged
// 64-code chunk. Exact chains, first-min tie-break. dyn smem: 64*257 floats.
// ---------------------------------------------------------------------------
__global__ __launch_bounds__(256) void refine_full(const float* __restrict__ cb)
{
    extern __shared__ float scf[];          // [64][257]
    __shared__ float sx[8][260];
    __shared__ float x2s[8];
    __shared__ int   rown[8];
    __shared__ float c2s[K_];
    __shared__ float bvS[8][64];
    __shared__ int   biS[8][64];
    const int t = threadIdx.x;
    const int cnt = g_qb_n;
    const int c = t & 63, r = t >> 6;

#pragma unroll
    for (int i = 0; i < 4; ++i) c2s[t + (i << 8)] = g_c2[t + (i << 8)];

    for (int q0 = blockIdx.x * 8; q0 < cnt; q0 += gridDim.x * 8) {
        const int nrows = min(8, cnt - q0);
        __syncthreads();
        if (t < 8 && t < nrows) {
            const int n = g_qb[q0 + t];
            rown[t] = n;
            x2s[t] = g_x2[n];
        }
#pragma unroll
        for (int i = 0; i < 2; ++i) {
            const int slot = t + (i << 8);
            const int rr = slot >> 6, d4 = (slot & 63) << 2;
            if (rr < nrows) {
                const int n = g_qb[q0 + rr];
                *(float4*)&sx[rr][d4] = *(const float4*)(g_xt + ((size_t)n << 8) + d4);
            }
        }

        float bv0 = FINF, bv1 = FINF;
        int   bi0 = 0x7fffffff, bi1 = 0x7fffffff;

        for (int nc = 0; nc < 16; ++nc) {
            __syncthreads();
#pragma unroll
            for (int i = 0; i < 16; ++i) {
                const int e = t + (i << 8);
                const int row = e >> 6, c4 = (e & 63) << 2;
                const float4 v = *(const float4*)(cb + ((size_t)((nc << 6) + row) << 8) + c4);
                float* dst = scf + row * 257 + c4;
                dst[0] = v.x; dst[1] = v.y; dst[2] = v.z; dst[3] = v.w;
            }
            __syncthreads();
            const int k = (nc << 6) + c;
            const float* cr = scf + c * 257;
            float s0 = 0.f, s1 = 0.f;
#pragma unroll 8
            for (int d = 0; d < D_; ++d) {
                const float cv = cr[d];
                s0 = fmaf(sx[r][d],     cv, s0);
                s1 = fmaf(sx[r + 4][d], cv, s1);
            }
            const float v0 = __fadd_rn(__fadd_rn(x2s[r],     -2.f * s0), c2s[k]);
            const float v1 = __fadd_rn(__fadd_rn(x2s[r + 4], -2.f * s1), c2s[k]);
            if (v0 < bv0) { bv0 = v0; bi0 = k; }
            if (v1 < bv1) { bv1 = v1; bi1 = k; }
        }

        bvS[r][c] = bv0;     biS[r][c] = bi0;
        bvS[r + 4][c] = bv1; biS[r + 4][c] = bi1;
        __syncthreads();

        const int w = t >> 5, l = t & 31;
        if (w < nrows) {
            float v = bvS[w][l];        int kk = biS[w][l];
            const float v2 = bvS[w][l + 32]; const int k2 = biS[w][l + 32];
            if (v2 < v || (v2 == v && k2 < kk)) { v = v2; kk = k2; }
#pragma unroll
            for (int m = 16; m; m >>= 1) {
                const float ov = __shfl_xor_sync(0xffffffffu, v, m);
                const int   oi = __shfl_xor_sync(0xffffffffu, kk, m);
                if (ov < v || (ov == v && oi < kk)) { v = ov; kk = oi; }
            }
            if (l == 0) g_idx[rown[w]] = kk;
        }
    }
}

// ---------------------------------------------------------------------------
// quant: gathered codebook rows staged to smem, straight-through output +
// loss partials + idx-as-float. dyn smem: 64*257 floats.
// ---------------------------------------------------------------------------
__global__ __launch_bounds__(256) void quant_kernel(
    const float* __restrict__ x, const float* __restrict__ cb,
    float* __restrict__ out, long long out_size)
{
    extern __shared__ float sc[];           // [64][257]
    __shared__ float red[256];
    __shared__ int   ks[64];
    const int t   = threadIdx.x;
    const int n0  = blockIdx.x * 64;
    const int b   = n0 / HW_;
    const int hw0 = n0 % HW_;
    const int tn  = t & 63;
    const int dz  = t >> 6;
    const int n   = n0 + tn;

    if (t < 64) ks[t] = g_idx[n0 + t];
    __syncthreads();

#pragma unroll
    for (int i = 0; i < 16; ++i) {
        const int e = t + (i << 8);
        const int row = e >> 6, f4 = (e & 63) << 2;
        const float4 v = *(const float4*)(cb + ((size_t)ks[row] << 8) + f4);
        float* dst = sc + row * 257 + f4;
        dst[0] = v.x; dst[1] = v.y; dst[2] = v.z; dst[3] = v.w;
    }
    __syncthreads();

    const float* xb = x   + (size_t)b * D_ * HW_ + hw0 + tn;
    float*       ob = out + (size_t)b * D_ * HW_ + hw0 + tn;
    const float* cr = sc + tn * 257;

    float s = 0.f;
#pragma unroll 8
    for (int d = dz; d < D_; d += 4) {
        const float xv   = xb[(size_t)d * HW_];
        const float cv   = cr[d];
        const float diff = __fadd_rn(cv, -xv);
        ob[(size_t)d * HW_] = __fadd_rn(xv, diff);
        s = fmaf(diff, diff, s);
    }

    if (dz == 0 && out_size >= Q_OFF + 3 + N_)
        out[Q_OFF + 3 + n] = (float)ks[tn];

    red[t] = s;
    __syncthreads();
    for (int w = 128; w > 0; w >>= 1) {
        if (t < w) red[t] += red[t + w];
        __syncthreads();
    }
    if (t == 0) atomicAdd(&g_acc, (double)red[0]);
}

__global__ void finalize_kernel(float* __restrict__ out, long long out_size) {
    if (out_size >= Q_OFF + 3) {
        const double m = g_acc / (double)((long long)N_ * D_);
        const float  l = (float)m;
        out[Q_OFF + 0] = l;
        out[Q_OFF + 1] = l;
        out[Q_OFF + 2] = __fadd_rn(l, 0.25f * l);
    }
}

// ---------------------------------------------------------------------------
extern "C" void kernel_launch(void* const* d_in, const int* in_sizes, int n_in,
                              void* d_out, int out_size)
{
    const float* x  = (const float*)d_in[0];
    const float* cb = (const float*)d_in[1];
    float*       out = (float*)d_out;
    const long long osz = (long long)out_size;

    cudaFuncSetAttribute(prep_x,
        cudaFuncAttributeMaxDynamicSharedMemorySize, 64 * 257 * 4);
    cudaFuncSetAttribute(gemm_argmin,
        cudaFuncAttributeMaxDynamicSharedMemorySize, GEMM_SMEM);
    cudaFuncSetAttribute(refine_full,
        cudaFuncAttributeMaxDynamicSharedMemorySize, 64 * 257 * 4);
    cudaFuncSetAttribute(quant_kernel,
        cudaFuncAttributeMaxDynamicSharedMemorySize, 64 * 257 * 4);

    prep_cb<<<K_, 256>>>(cb);                      // launch 1
    prep_x<<<512, 256, 64 * 257 * 4>>>(x);         // launch 2
    gemm_argmin<<<N_ / 128, 512, GEMM_SMEM>>>();   // launch 3
    refine_full<<<64, 256, 64 * 257 * 4>>>(cb);    // launch 4 (ncu target)
    refine_small<<<256, 256>>>(cb);                // launch 5
    quant_kernel<<<N_ / 64, 256, 64 * 257 * 4>>>(x, cb, out, osz);
    finalize_kernel<<<1, 1>>>(out, osz);
}

// round 17
// speedup vs baseline: 1.5004x; 1.0636x over previous
#include <cuda_runtime.h>
#include <cuda_fp16.h>
#include <cstdint>

#define B_   32
#define D_   256
#define HW_  1024
#define N_   32768
#define K_   1024
#define MARGIN 1.2e-4f
#define FINF 3.4e38f

static const long long Q_OFF = 8388608LL;   // B*D*H*W

// ---------------- device globals ----------------
__device__ int    g_idx[N_];
__device__ float  g_c2[K_];
__device__ float  g_x2[N_];
__device__ double g_acc;
__device__ __align__(16) __half g_xh[(size_t)N_ * D_];
__device__ __align__(16) __half g_ch[(size_t)K_ * D_];
__device__ float g_cv[N_][4];   // queue-A rows only (c2 - 2s)
__device__ int   g_ci[N_][4];
__device__ int   g_qa[N_];
__device__ int   g_qb[N_];
__device__ int   g_qa_n;
__device__ int   g_qb_n;

__device__ __forceinline__ uint32_t smem_u32(const void* p) {
    uint32_t a;
    asm("{ .reg .u64 t; cvta.to.shared.u64 t, %1; cvt.u32.u64 %0, t; }"
        : "=r"(a) : "l"(p));
    return a;
}
#define LDSM_X4(r0, r1, r2, r3, addr) \
    asm volatile("ldmatrix.sync.aligned.m8n8.x4.shared.b16 {%0,%1,%2,%3}, [%4];" \
                 : "=r"(r0), "=r"(r1), "=r"(r2), "=r"(r3) : "r"(addr))
#define MMA_F16(c, a0, a1, a2, a3, b0, b1) \
    asm volatile("mma.sync.aligned.m16n8k16.row.col.f32.f16.f16.f32 " \
                 "{%0,%1,%2,%3}, {%4,%5,%6,%7}, {%8,%9}, {%0,%1,%2,%3};" \
                 : "+f"((c)[0]), "+f"((c)[1]), "+f"((c)[2]), "+f"((c)[3]) \
                 : "r"(a0), "r"(a1), "r"(a2), "r"(a3), "r"(b0), "r"(b1))
#define CP_ASYNC16(dst, src) \
    asm volatile("cp.async.cg.shared.global [%0], [%1], 16;" \
                 :: "r"(dst), "l"(src))
#define CP_COMMIT() asm volatile("cp.async.commit_group;" ::: "memory")
#define CP_WAIT(n)  asm volatile("cp.async.wait_group %0;" :: "n"(n) : "memory")

__device__ __forceinline__ void fold4(float* v, int* ix, float nv, int nk) {
    if (nv < v[3]) {
        if (nv < v[2]) {
            v[3] = v[2]; ix[3] = ix[2];
            if (nv < v[1]) {
                v[2] = v[1]; ix[2] = ix[1];
                if (nv < v[0]) { v[1] = v[0]; ix[1] = ix[0]; v[0] = nv; ix[0] = nk; }
                else           { v[1] = nv; ix[1] = nk; }
            } else { v[2] = nv; ix[2] = nk; }
        } else { v[3] = nv; ix[3] = nk; }
    }
}

// ---------------------------------------------------------------------------
__global__ void zero_kernel() { g_acc = 0.0; g_qa_n = 0; g_qb_n = 0; }

// ---------------------------------------------------------------------------
// prep_cb: fp16 convert; exact c2 (sequential no-FMA).
// ---------------------------------------------------------------------------
__global__ __launch_bounds__(256) void prep_cb(const float* __restrict__ cb) {
    __shared__ float row[256];
    const int k = blockIdx.x, t = threadIdx.x;
    const float v = cb[(size_t)k * D_ + t];
    row[t] = v;
    g_ch[(size_t)k * D_ + t] = __float2half_rn(v);
    __syncthreads();
    if (t == 0) {
        float s = 0.f;
        for (int d = 0; d < D_; ++d)
            s = __fadd_rn(s, __fmul_rn(row[d], row[d]));
        g_c2[k] = s;
    }
}

// ---------------------------------------------------------------------------
// prep_x: transpose to smem, exact x2 (warps 0-1), half2 writes of g_xh only.
// dyn smem: 64*257 floats.
// ---------------------------------------------------------------------------
__global__ __launch_bounds__(256) void prep_x(const float* __restrict__ x) {
    extern __shared__ float xs[];   // [64 n][257 d]
    const int t   = threadIdx.x;
    const int n0  = blockIdx.x * 64;
    const int b   = n0 >> 10;
    const int hw0 = n0 & 1023;
    const float* xb = x + ((size_t)b << 18) + hw0;

#pragma unroll
    for (int i = 0; i < 16; ++i) {
        const int e  = t + (i << 8);
        const int d  = e >> 4;
        const int n4 = (e & 15) << 2;
        const float4 v = *(const float4*)(xb + ((size_t)d << 10) + n4);
        xs[(n4 + 0) * 257 + d] = v.x;
        xs[(n4 + 1) * 257 + d] = v.y;
        xs[(n4 + 2) * 257 + d] = v.z;
        xs[(n4 + 3) * 257 + d] = v.w;
    }
    __syncthreads();

    if (t < 64) {
        const float* r = xs + t * 257;
        float s = 0.f;
        for (int d = 0; d < D_; ++d)
            s = __fadd_rn(s, __fmul_rn(r[d], r[d]));
        g_x2[n0 + t] = s;
    }

#pragma unroll
    for (int i = 0; i < 32; ++i) {
        const int e  = t + (i << 8);
        const int n  = e >> 7;
        const int d2 = (e & 127) << 1;
        *(__half2*)(g_xh + ((size_t)(n0 + n) << 8) + d2) =
            __floats2half2_rn(xs[n * 257 + d2], xs[n * 257 + d2 + 1]);
    }
}

// ---------------------------------------------------------------------------
// gemm_argmin: single-pass fp16 HMMA (s = xh*ch), x2-free epilogue with
// fminf branch-elision guard; classification fused into the tail.
// 128-row CTA, 512 threads = 16 warps (4M x 4N), 128-code B chunks
// cp.async double-buffered.
// ---------------------------------------------------------------------------
#define PITCH 264
#define SA        0
#define SB        (128 * PITCH * 2)               // 67584
#define SB_STRIDE (128 * PITCH * 2)               // 67584 per buffer
#define S_C2      (SB + 2 * SB_STRIDE)            // 202752
#define S_MGV     (S_C2 + 4096)                   // 206848
#define S_MGI     (S_MGV + 8192)                  // 215040
#define GEMM_SMEM (S_MGI + 8192)                  // 223232

__device__ __forceinline__ void stage_b(uint32_t sb, int buf, int kc, int t) {
    const uint32_t dst = sb + SB + buf * SB_STRIDE;
#pragma unroll
    for (int i = 0; i < 8; ++i) {
        const int e = t + (i << 9);               // 0..4095
        const int row = e >> 5;                   // 0..127
        const int c8 = (e & 31) << 3;             // 0..248
        CP_ASYNC16(dst + (uint32_t)(row * PITCH + c8) * 2,
                   g_ch + (((size_t)((kc << 7) + row)) << 8) + c8);
    }
}

__global__ __launch_bounds__(512, 1) void gemm_argmin() {
    extern __shared__ char sm[];
    __half* Ah = (__half*)(sm + SA);
    float* c2s = (float*)(sm + S_C2);
    float* mgv = (float*)(sm + S_MGV);
    int*   mgi = (int*)(sm + S_MGI);

    const int t    = threadIdx.x;
    const int lane = t & 31;
    const int w    = t >> 5;                      // 0..15
    const int wm   = (w >> 2) << 5;               // M base row
    const int wq   = w & 3;                       // N quarter
    const int n0   = blockIdx.x * 128;
    const int g = lane >> 2, q = lane & 3;
    const uint32_t sb = smem_u32(sm);

    stage_b(sb, 0, 0, t);
    CP_COMMIT();

#pragma unroll
    for (int i = 0; i < 8; ++i) {
        const int e = t + (i << 9);
        const int row = e >> 5, c8 = (e & 31) << 3;
        *(uint4*)(Ah + row * PITCH + c8) =
            *(const uint4*)(g_xh + ((size_t)(n0 + row) << 8) + c8);
    }
#pragma unroll
    for (int i = 0; i < 2; ++i) c2s[t + (i << 9)] = g_c2[t + (i << 9)];

    const uint32_t a_idx = (uint32_t)((wm + (lane & 15)) * PITCH + ((lane >> 4) << 3));
    const uint32_t aoh = sb + SA + a_idx * 2;
    const uint32_t b_idx = (uint32_t)(((lane & 7) + ((lane >> 4) << 3)) * PITCH
                                      + (((lane >> 3) & 1) << 3));
    const uint32_t bgrp = (uint32_t)((wq << 5) * PITCH) * 2;
    const int col_off = (wq << 5) + (q << 1);

    float tv[4][4];
    int   ti[4][4];
#pragma unroll
    for (int r = 0; r < 4; ++r)
#pragma unroll
        for (int s = 0; s < 4; ++s) { tv[r][s] = FINF; ti[r][s] = 0; }

    for (int nc = 0; nc < 8; ++nc) {
        const int buf = nc & 1;
        if (nc < 7) { stage_b(sb, buf ^ 1, nc + 1, t); CP_COMMIT(); CP_WAIT(1); }
        else        { CP_WAIT(0); }
        __syncthreads();

        const uint32_t bh = sb + SB + buf * SB_STRIDE + bgrp + b_idx * 2;

        float acc[2][4][4];
#pragma unroll
        for (int mh = 0; mh < 2; ++mh)
#pragma unroll
            for (int j = 0; j < 4; ++j)
#pragma unroll
                for (int s = 0; s < 4; ++s) acc[mh][j][s] = 0.f;

#pragma unroll 8
        for (int k = 0; k < 16; ++k) {
            uint32_t a00, a01, a02, a03, a10, a11, a12, a13;
            uint32_t h00, h01, h02, h03, h10, h11, h12, h13;
            LDSM_X4(a00, a01, a02, a03, aoh + k * 32);
            LDSM_X4(a10, a11, a12, a13, aoh + 16 * PITCH * 2 + k * 32);
            LDSM_X4(h00, h01, h02, h03, bh + k * 32);
            LDSM_X4(h10, h11, h12, h13, bh + 16 * PITCH * 2 + k * 32);
            MMA_F16(acc[0][0], a00, a01, a02, a03, h00, h01);
            MMA_F16(acc[0][1], a00, a01, a02, a03, h02, h03);
            MMA_F16(acc[0][2], a00, a01, a02, a03, h10, h11);
            MMA_F16(acc[0][3], a00, a01, a02, a03, h12, h13);
            MMA_F16(acc[1][0], a10, a11, a12, a13, h00, h01);
            MMA_F16(acc[1][1], a10, a11, a12, a13, h02, h03);
            MMA_F16(acc[1][2], a10, a11, a12, a13, h10, h11);
            MMA_F16(acc[1][3], a10, a11, a12, a13, h12, h13);
        }

        const int colb0 = (nc << 7) + col_off;
#pragma unroll
        for (int mh = 0; mh < 2; ++mh) {
#pragma unroll
            for (int half = 0; half < 2; ++half) {
                const int r = mh * 2 + half;
                float vv[8];
#pragma unroll
                for (int j = 0; j < 4; ++j) {
                    const int colb = colb0 + (j << 3);
                    vv[2 * j]     = fmaf(-2.f, acc[mh][j][2 * half],     c2s[colb]);
                    vv[2 * j + 1] = fmaf(-2.f, acc[mh][j][2 * half + 1], c2s[colb + 1]);
                }
                float vmin = vv[0];
#pragma unroll
                for (int s = 1; s < 8; ++s) vmin = fminf(vmin, vv[s]);
                if (vmin < tv[r][3]) {
#pragma unroll
                    for (int j = 0; j < 4; ++j) {
                        const int colb = colb0 + (j << 3);
                        fold4(tv[r], ti[r], vv[2 * j],     colb);
                        fold4(tv[r], ti[r], vv[2 * j + 1], colb + 1);
                    }
                }
            }
        }
        __syncthreads();
    }

#pragma unroll
    for (int r = 0; r < 4; ++r) {
#pragma unroll
        for (int m = 1; m <= 2; m <<= 1) {
            float ov[4]; int oi[4];
#pragma unroll
            for (int s = 0; s < 4; ++s) {
                ov[s] = __shfl_xor_sync(0xffffffffu, tv[r][s], m);
                oi[s] = __shfl_xor_sync(0xffffffffu, ti[r][s], m);
            }
#pragma unroll
            for (int s = 0; s < 4; ++s) fold4(tv[r], ti[r], ov[s], oi[s]);
        }
    }
    if (q == 0) {
#pragma unroll
        for (int r = 0; r < 4; ++r) {
            const int row = wm + ((r & 1) << 3) + ((r >> 1) << 4) + g;
#pragma unroll
            for (int s = 0; s < 4; ++s) {
                mgv[(row * 4 + wq) * 4 + s] = tv[r][s];
                mgi[(row * 4 + wq) * 4 + s] = ti[r][s];
            }
        }
    }
    __syncthreads();
    if (t < 128) {
        float bv[4] = {FINF, FINF, FINF, FINF};
        int   bi[4] = {0, 0, 0, 0};
#pragma unroll
        for (int qq = 0; qq < 4; ++qq)
#pragma unroll
            for (int s = 0; s < 4; ++s)
                fold4(bv, bi, mgv[(t * 4 + qq) * 4 + s], mgi[(t * 4 + qq) * 4 + s]);
        const int n = n0 + t;
        const float lim = bv[0] + MARGIN;
        const int ncand = 1 + (bv[1] <= lim) + (bv[2] <= lim) + (bv[3] <= lim);
        if (ncand == 1) {
            g_idx[n] = bi[0];
        } else if (ncand < 4) {
#pragma unroll
            for (int s = 0; s < 4; ++s) { g_cv[n][s] = bv[s]; g_ci[n][s] = bi[s]; }
            g_qa[atomicAdd(&g_qa_n, 1)] = n;
        } else {
            g_qb[atomicAdd(&g_qb_n, 1)] = n;
        }
    }
}

// ---------------------------------------------------------------------------
// refine_small: persistent warps over queue A; x row staged from original
// (B,D,H,W) layout (strided gather, queue is tiny).
// ---------------------------------------------------------------------------
__global__ __launch_bounds__(256) void refine_small(
    const float* __restrict__ x, const float* __restrict__ cb)
{
    __shared__ float sx[8][260];
    __shared__ float sc[8][3][260];
    const int w = threadIdx.x >> 5;
    const int l = threadIdx.x & 31;
    const int wi = (blockIdx.x << 3) + w;
    const int stride = gridDim.x << 3;
    const int cnt = g_qa_n;

    for (int i = wi; i < cnt; i += stride) {
        const int n = g_qa[i];
        const float lim = g_cv[n][0] + MARGIN;
        const int ncand = 2 + (g_cv[n][2] <= lim);

        {
            const float* xp = x + (((size_t)(n >> 10)) << 18) + (n & 1023);
#pragma unroll
            for (int ii = 0; ii < 8; ++ii) {
                const int d = l + (ii << 5);
                sx[w][d] = xp[(size_t)d << 10];
            }
        }
        for (int c = 0; c < ncand; ++c) {
            const float* cr = cb + ((size_t)g_ci[n][c] << 8);
#pragma unroll
            for (int ii = 0; ii < 2; ++ii) {
                const int d = (l + (ii << 5)) << 2;
                *(float4*)&sc[w][c][d] = *(const float4*)(cr + d);
            }
        }
        __syncwarp();

        float bestv = FINF;
        int   besti = 0x7fffffff;
        if (l < ncand) {
            const int k = g_ci[n][l];
            float s = 0.f;
#pragma unroll 16
            for (int d = 0; d < D_; ++d)
                s = fmaf(sx[w][d], sc[w][l][d], s);
            bestv = __fadd_rn(__fadd_rn(g_x2[n], -2.f * s), g_c2[k]);
            besti = k;
        }
#pragma unroll
        for (int m = 16; m; m >>= 1) {
            const float ov = __shfl_xor_sync(0xffffffffu, bestv, m);
            const int   oi = __shfl_xor_sync(0xffffffffu, besti, m);
            if (ov < bestv || (ov == bestv && oi < besti)) { bestv = ov; besti = oi; }
        }
        if (l == 0) g_idx[n] = besti;
        __syncwarp();
    }
}

// ---------------------------------------------------------------------------
// refine_full (batched): 8 saturated rows per block share each staged
// 64-code chunk; x rows staged from original layout. dyn smem: 64*257 floats.
// ---------------------------------------------------------------------------
__global__ __launch_bounds__(256) void refine_full(
    const float* __restrict__ x, const float* __restrict__ cb)
{
    extern __shared__ float scf[];          // [64][257]
    __shared__ float sx[8][260];
    __shared__ float x2s[8];
    __shared__ int   rown[8];
    __shared__ float c2s[K_];
    __shared__ float bvS[8][64];
    __shared__ int   biS[8][64];
    const int t = threadIdx.x;
    const int cnt = g_qb_n;
    const int c = t & 63, r = t >> 6;

#pragma unroll
    for (int i = 0; i < 4; ++i) c2s[t + (i << 8)] = g_c2[t + (i << 8)];

    for (int q0 = blockIdx.x * 8; q0 < cnt; q0 += gridDim.x * 8) {
        const int nrows = min(8, cnt - q0);
        __syncthreads();
        if (t < 8 && t < nrows) {
            const int n = g_qb[q0 + t];
            rown[t] = n;
            x2s[t] = g_x2[n];
        }
        __syncthreads();
        {
            const int rr = t >> 5, l = t & 31;     // 8 rows x 32 lanes
            if (rr < nrows) {
                const int n = rown[rr];
                const float* xp = x + (((size_t)(n >> 10)) << 18) + (n & 1023);
#pragma unroll
                for (int j = 0; j < 8; ++j) {
                    const int d = l + (j << 5);
                    sx[rr][d] = xp[(size_t)d << 10];
                }
            }
        }

        float bv0 = FINF, bv1 = FINF;
        int   bi0 = 0x7fffffff, bi1 = 0x7fffffff;

        for (int nc = 0; nc < 16; ++nc) {
            __syncthreads();
#pragma unroll
            for (int i = 0; i < 16; ++i) {
                const int e = t + (i << 8);
                const int row = e >> 6, c4 = (e & 63) << 2;
                const float4 v = *(const float4*)(cb + ((size_t)((nc << 6) + row) << 8) + c4);
                float* dst = scf + row * 257 + c4;
                dst[0] = v.x; dst[1] = v.y; dst[2] = v.z; dst[3] = v.w;
            }
            __syncthreads();
            const int k = (nc << 6) + c;
            const float* cr = scf + c * 257;
            float s0 = 0.f, s1 = 0.f;
#pragma unroll 8
            for (int d = 0; d < D_; ++d) {
                const float cv = cr[d];
                s0 = fmaf(sx[r][d],     cv, s0);
                s1 = fmaf(sx[r + 4][d], cv, s1);
            }
            const float v0 = __fadd_rn(__fadd_rn(x2s[r],     -2.f * s0), c2s[k]);
            const float v1 = __fadd_rn(__fadd_rn(x2s[r + 4], -2.f * s1), c2s[k]);
            if (v0 < bv0) { bv0 = v0; bi0 = k; }
            if (v1 < bv1) { bv1 = v1; bi1 = k; }
        }

        bvS[r][c] = bv0;     biS[r][c] = bi0;
        bvS[r + 4][c] = bv1; biS[r + 4][c] = bi1;
        __syncthreads();

        const int w = t >> 5, l = t & 31;
        if (w < nrows) {
            float v = bvS[w][l];        int kk = biS[w][l];
            const float v2 = bvS[w][l + 32]; const int k2 = biS[w][l + 32];
            if (v2 < v || (v2 == v && k2 < kk)) { v = v2; kk = k2; }
#pragma unroll
            for (int m = 16; m; m >>= 1) {
                const float ov = __shfl_xor_sync(0xffffffffu, v, m);
                const int   oi = __shfl_xor_sync(0xffffffffu, kk, m);
                if (ov < v || (ov == v && oi < kk)) { v = ov; kk = oi; }
            }
            if (l == 0) g_idx[rown[w]] = kk;
        }
    }
}

// ---------------------------------------------------------------------------
// quant: gathered codebook rows staged to smem, straight-through output +
// loss partials + idx-as-float. dyn smem: 64*257 floats.
// ---------------------------------------------------------------------------
__global__ __launch_bounds__(256) void quant_kernel(
    const float* __restrict__ x, const float* __restrict__ cb,
    float* __restrict__ out, long long out_size)
{
    extern __shared__ float sc[];           // [64][257]
    __shared__ float red[256];
    __shared__ int   ks[64];
    const int t   = threadIdx.x;
    const int n0  = blockIdx.x * 64;
    const int b   = n0 / HW_;
    const int hw0 = n0 % HW_;
    const int tn  = t & 63;
    const int dz  = t >> 6;
    const int n   = n0 + tn;

    if (t < 64) ks[t] = g_idx[n0 + t];
    __syncthreads();

#pragma unroll
    for (int i = 0; i < 16; ++i) {
        const int e = t + (i << 8);
        const int row = e >> 6, f4 = (e & 63) << 2;
        const float4 v = *(const float4*)(cb + ((size_t)ks[row] << 8) + f4);
        float* dst = sc + row * 257 + f4;
        dst[0] = v.x; dst[1] = v.y; dst[2] = v.z; dst[3] = v.w;
    }
    __syncthreads();

    const float* xb = x   + (size_t)b * D_ * HW_ + hw0 + tn;
    float*       ob = out + (size_t)b * D_ * HW_ + hw0 + tn;
    const float* cr = sc + tn * 257;

    float s = 0.f;
#pragma unroll 8
    for (int d = dz; d < D_; d += 4) {
        const float xv   = xb[(size_t)d * HW_];
        const float cv   = cr[d];
        const float diff = __fadd_rn(cv, -xv);
        ob[(size_t)d * HW_] = __fadd_rn(xv, diff);
        s = fmaf(diff, diff, s);
    }

    if (dz == 0 && out_size >= Q_OFF + 3 + N_)
        out[Q_OFF + 3 + n] = (float)ks[tn];

    red[t] = s;
    __syncthreads();
    for (int w = 128; w > 0; w >>= 1) {
        if (t < w) red[t] += red[t + w];
        __syncthreads();
    }
    if (t == 0) atomicAdd(&g_acc, (double)red[0]);
}

__global__ void finalize_kernel(float* __restrict__ out, long long out_size) {
    if (out_size >= Q_OFF + 3) {
        const double m = g_acc / (double)((long long)N_ * D_);
        const float  l = (float)m;
        out[Q_OFF + 0] = l;
        out[Q_OFF + 1] = l;
        out[Q_OFF + 2] = __fadd_rn(l, 0.25f * l);
    }
}

// ---------------------------------------------------------------------------
extern "C" void kernel_launch(void* const* d_in, const int* in_sizes, int n_in,
                              void* d_out, int out_size)
{
    const float* x  = (const float*)d_in[0];
    const float* cb = (const float*)d_in[1];
    float*       out = (float*)d_out;
    const long long osz = (long long)out_size;

    cudaFuncSetAttribute(prep_x,
        cudaFuncAttributeMaxDynamicSharedMemorySize, 64 * 257 * 4);
    cudaFuncSetAttribute(gemm_argmin,
        cudaFuncAttributeMaxDynamicSharedMemorySize, GEMM_SMEM);
    cudaFuncSetAttribute(refine_full,
        cudaFuncAttributeMaxDynamicSharedMemorySize, 64 * 257 * 4);
    cudaFuncSetAttribute(quant_kernel,
        cudaFuncAttributeMaxDynamicSharedMemorySize, 64 * 257 * 4);

    zero_kernel<<<1, 1>>>();                       // launch 1
    prep_cb<<<K_, 256>>>(cb);                      // launch 2
    prep_x<<<512, 256, 64 * 257 * 4>>>(x);         // launch 3
    gemm_argmin<<<N_ / 128, 512, GEMM_SMEM>>>();   // launch 4 (ncu target)
    refine_small<<<256, 256>>>(x, cb);             // launch 5
    refine_full<<<64, 256, 64 * 257 * 4>>>(x, cb); // launch 6
    quant_kernel<<<N_ / 64, 256, 64 * 257 * 4>>>(x, cb, out, osz);
    finalize_kernel<<<1, 1>>>(out, osz);
}